// round 15
// baseline (speedup 1.0000x reference)
#include <cuda_runtime.h>
#include <cuda_bf16.h>
#include <math.h>
#include <stdint.h>

// Swin-style window cross-attention.
// B=128, N=256 (16x16 window), C=512, H=8, d=64.
// GEMMs: 3-term compensated split-bf16 mma.sync (drop lo*lo).
// Activations/weights pre-split ONCE; GEMM staging is raw bf16 copies.
// RULE: device globals are referenced ONLY inside device code — kernel_launch
// passes only harness-provided pointers.

// ---------------- scratch (device globals; no allocation) ------------------
__device__ float g_qlin [32768LL * 512];    // [B*N, C] fp32
__device__ float g_kvlin[32768LL * 1024];   // [B*N, 2C] fp32
__device__ float g_o    [32768LL * 512];    // [B,N,C] fp32 (head-interleaved)
__device__ float g_bias [8LL * 256 * 256];  // [H,N,N]
// split activation pair (holds x, then y, then o — strictly sequential)
__device__ __nv_bfloat16 g_inh[32768LL * 512];
__device__ __nv_bfloat16 g_inl[32768LL * 512];
// split weights
__device__ __nv_bfloat16 g_wqh [512LL * 512],  g_wql [512LL * 512];
__device__ __nv_bfloat16 g_wkvh[512LL * 1024], g_wkvl[512LL * 1024];
__device__ __nv_bfloat16 g_wph [512LL * 512],  g_wpl [512LL * 512];

// ---------------------------- helpers --------------------------------------
__device__ __forceinline__ uint32_t smem_u32(const void* p) {
    return (uint32_t)__cvta_generic_to_shared(p);
}
__device__ __forceinline__ uint32_t pack_bf2(float a, float b) {
    __nv_bfloat162 t = __floats2bfloat162_rn(a, b);
    return *reinterpret_cast<uint32_t*>(&t);
}
__device__ __forceinline__ void ldm_x4(uint32_t* r, uint32_t addr) {
    asm volatile("ldmatrix.sync.aligned.m8n8.x4.shared.b16 {%0,%1,%2,%3}, [%4];"
                 : "=r"(r[0]), "=r"(r[1]), "=r"(r[2]), "=r"(r[3]) : "r"(addr));
}
__device__ __forceinline__ void ldm_x4_t(uint32_t* r, uint32_t addr) {
    asm volatile("ldmatrix.sync.aligned.m8n8.x4.trans.shared.b16 {%0,%1,%2,%3}, [%4];"
                 : "=r"(r[0]), "=r"(r[1]), "=r"(r[2]), "=r"(r[3]) : "r"(addr));
}
__device__ __forceinline__ void mma_bf16(float* c, const uint32_t* a, const uint32_t* b) {
    asm volatile(
        "mma.sync.aligned.m16n8k16.row.col.f32.bf16.bf16.f32 "
        "{%0,%1,%2,%3}, {%4,%5,%6,%7}, {%8,%9}, {%0,%1,%2,%3};"
        : "+f"(c[0]), "+f"(c[1]), "+f"(c[2]), "+f"(c[3])
        : "r"(a[0]), "r"(a[1]), "r"(a[2]), "r"(a[3]), "r"(b[0]), "r"(b[1]));
}

// ---------------------------------------------------------------------------
// fp32 -> (hi, lo) bf16 split body; wrappers bind device-global destinations.
// ---------------------------------------------------------------------------
__device__ __forceinline__ void
split_body(const float4* __restrict__ src, uint2* __restrict__ hi,
           uint2* __restrict__ lo, int n4)
{
    int i = blockIdx.x * blockDim.x + threadIdx.x;
    if (i >= n4) return;
    float4 v = src[i];
    float h0 = __bfloat162float(__float2bfloat16_rn(v.x));
    float h1 = __bfloat162float(__float2bfloat16_rn(v.y));
    float h2 = __bfloat162float(__float2bfloat16_rn(v.z));
    float h3 = __bfloat162float(__float2bfloat16_rn(v.w));
    hi[i] = make_uint2(pack_bf2(h0, h1), pack_bf2(h2, h3));
    lo[i] = make_uint2(pack_bf2(v.x - h0, v.y - h1), pack_bf2(v.z - h2, v.w - h3));
}

__global__ void __launch_bounds__(256)
k_split_in(const float4* __restrict__ src)   // x or y -> g_inh/g_inl
{
    split_body(src, (uint2*)g_inh, (uint2*)g_inl, 4194304);
}
__global__ void __launch_bounds__(256)
k_split_o()                                   // g_o -> g_inh/g_inl
{
    split_body((const float4*)g_o, (uint2*)g_inh, (uint2*)g_inl, 4194304);
}
__global__ void __launch_bounds__(256)
k_split_wq(const float4* __restrict__ w)
{
    split_body(w, (uint2*)g_wqh, (uint2*)g_wql, 65536);
}
__global__ void __launch_bounds__(256)
k_split_wkv(const float4* __restrict__ w)
{
    split_body(w, (uint2*)g_wkvh, (uint2*)g_wkvl, 131072);
}
__global__ void __launch_bounds__(256)
k_split_wp(const float4* __restrict__ w)
{
    split_body(w, (uint2*)g_wph, (uint2*)g_wpl, 65536);
}

// ---------------------------------------------------------------------------
// Split-bf16 tensor-core GEMM: C[M,N] = A[M,K] @ B[K,N] (+ optional col bias).
// Operands pre-split bf16 (hi/lo); staging is raw LDG/STS copies.
// CTA tile 128x128, BK=32, 256 threads, 8 warps (4m x 2n), warp 32x64.
// Mainloop/epilogue identical to the R8-passing kernel.
// ---------------------------------------------------------------------------
template<int EPI, int M, int N, int K, int LDA, int LDB, int LDC>
__device__ __forceinline__ void
mma_gemm_body(const __nv_bfloat16* __restrict__ Ah, const __nv_bfloat16* __restrict__ Al,
              const __nv_bfloat16* __restrict__ Bh, const __nv_bfloat16* __restrict__ Bl,
              float* __restrict__ C, const float* __restrict__ bias)
{
    constexpr int BK  = 32;
    constexpr int PA  = 40;
    constexpr int PB  = 136;

    __shared__ __nv_bfloat16 sAh[128 * PA];
    __shared__ __nv_bfloat16 sAl[128 * PA];
    __shared__ __nv_bfloat16 sBh[BK * PB];
    __shared__ __nv_bfloat16 sBl[BK * PB];

    const int tid  = threadIdx.x;
    const int wid  = tid >> 5;
    const int lane = tid & 31;
    const int wm   = wid >> 1;
    const int wn   = wid & 1;
    const int row0 = blockIdx.y * 128;
    const int col0 = blockIdx.x * 128;

    float acc[2][8][4];
    #pragma unroll
    for (int i = 0; i < 2; i++)
        #pragma unroll
        for (int j = 0; j < 8; j++)
            #pragma unroll
            for (int q = 0; q < 4; q++) acc[i][j][q] = 0.0f;

    const int ar  = tid >> 3;          // 0..31 (A rows, step 32)
    const int ac4 = (tid & 7) * 4;     // A col (4-elem granule)
    const int br  = tid >> 5;          // 0..7  (B rows, step 8)
    const int bc4 = (tid & 31) * 4;    // B col

    for (int k0 = 0; k0 < K; k0 += BK) {
        #pragma unroll
        for (int i = 0; i < 4; i++) {
            int r = ar + i * 32;
            long long ga = (long long)(row0 + r) * LDA + k0 + ac4;
            *(uint2*)&sAh[r * PA + ac4] = *(const uint2*)(Ah + ga);
            *(uint2*)&sAl[r * PA + ac4] = *(const uint2*)(Al + ga);
        }
        #pragma unroll
        for (int i = 0; i < 4; i++) {
            int rb = br + i * 8;
            long long gb = (long long)(k0 + rb) * LDB + col0 + bc4;
            *(uint2*)&sBh[rb * PB + bc4] = *(const uint2*)(Bh + gb);
            *(uint2*)&sBl[rb * PB + bc4] = *(const uint2*)(Bl + gb);
        }
        __syncthreads();

        #pragma unroll
        for (int ks = 0; ks < 2; ks++) {
            const int arow = wm * 32 + (lane & 15);
            const int acol = ks * 16 + ((lane >> 4) << 3);
            const int brow = ks * 16 + (lane & 15);

            uint32_t ah[2][4], al[2][4], bb[8][2];

            #pragma unroll
            for (int mf = 0; mf < 2; mf++)
                ldm_x4(ah[mf], smem_u32(&sAh[(arow + mf*16)*PA + acol]));
            #pragma unroll
            for (int np = 0; np < 4; np++) {
                uint32_t r[4];
                int bcol = wn * 64 + np * 16 + ((lane >> 4) << 3);
                ldm_x4_t(r, smem_u32(&sBh[brow*PB + bcol]));
                bb[2*np][0] = r[0]; bb[2*np][1] = r[1];
                bb[2*np+1][0] = r[2]; bb[2*np+1][1] = r[3];
            }
            #pragma unroll
            for (int mf = 0; mf < 2; mf++)
                #pragma unroll
                for (int nf = 0; nf < 8; nf++)
                    mma_bf16(acc[mf][nf], ah[mf], bb[nf]);

            #pragma unroll
            for (int mf = 0; mf < 2; mf++)
                ldm_x4(al[mf], smem_u32(&sAl[(arow + mf*16)*PA + acol]));
            #pragma unroll
            for (int mf = 0; mf < 2; mf++)
                #pragma unroll
                for (int nf = 0; nf < 8; nf++)
                    mma_bf16(acc[mf][nf], al[mf], bb[nf]);

            #pragma unroll
            for (int np = 0; np < 4; np++) {
                uint32_t r[4];
                int bcol = wn * 64 + np * 16 + ((lane >> 4) << 3);
                ldm_x4_t(r, smem_u32(&sBl[brow*PB + bcol]));
                bb[2*np][0] = r[0]; bb[2*np][1] = r[1];
                bb[2*np+1][0] = r[2]; bb[2*np+1][1] = r[3];
            }
            #pragma unroll
            for (int mf = 0; mf < 2; mf++)
                #pragma unroll
                for (int nf = 0; nf < 8; nf++)
                    mma_bf16(acc[mf][nf], ah[mf], bb[nf]);
        }
        __syncthreads();
    }

    #pragma unroll
    for (int mf = 0; mf < 2; mf++) {
        #pragma unroll
        for (int nf = 0; nf < 8; nf++) {
            int r = row0 + wm*32 + mf*16 + (lane >> 2);
            int c = col0 + wn*64 + nf*8 + (lane & 3)*2;
            float2 v0 = { acc[mf][nf][0], acc[mf][nf][1] };
            float2 v1 = { acc[mf][nf][2], acc[mf][nf][3] };
            if (EPI == 1) {
                v0.x += bias[c]; v0.y += bias[c + 1];
                v1.x += bias[c]; v1.y += bias[c + 1];
            }
            *(float2*)(C + (long long)r*LDC + c)     = v0;
            *(float2*)(C + (long long)(r+8)*LDC + c) = v1;
        }
    }
}

// GEMM wrappers: bind device globals INSIDE device code.
__global__ void __launch_bounds__(256)
k_gemm_q()
{
    mma_gemm_body<0, 32768,512,512, 512,512,512>(
        g_inh, g_inl, g_wqh, g_wql, g_qlin, nullptr);
}

__global__ void __launch_bounds__(256)
k_gemm_kv()
{
    mma_gemm_body<0, 32768,1024,512, 512,1024,1024>(
        g_inh, g_inl, g_wkvh, g_wkvl, g_kvlin, nullptr);
}

__global__ void __launch_bounds__(256)
k_gemm_proj(const float* __restrict__ proj_b, float* __restrict__ out)
{
    mma_gemm_body<1, 32768,512,512, 512,512,512>(
        g_inh, g_inl, g_wph, g_wpl, out, proj_b);
}

// ---------------------------------------------------------------------------
// Fused attention, tensor-core version (identical to the R8/R9-passing
// kernel). CTA = (q-tile 64, head, batch); 128 threads = 4 warps; warp owns
// 16 q-rows and the full 256-wide score stripe (softmax in registers).
// smem (dynamic, 90KB): Qh/Ql [64][72] bf16, Kh/Kl [256][72] bf16 (reused V).
// ---------------------------------------------------------------------------
__global__ void __launch_bounds__(128)
k_attn_fused()
{
    constexpr int PQ = 72;
    constexpr int PK = 72;

    extern __shared__ __nv_bfloat16 smb[];
    __nv_bfloat16* sQh = smb;
    __nv_bfloat16* sQl = smb + 4608;
    __nv_bfloat16* sKh = smb + 9216;
    __nv_bfloat16* sKl = smb + 27648;

    const int tid  = threadIdx.x;
    const int wid  = tid >> 5;
    const int lane = tid & 31;
    const int qt   = blockIdx.x;
    const int h    = blockIdx.y;
    const int b    = blockIdx.z;

    const long long qbase = (long long)b*131072 + (long long)(qt*64)*512 + h*64;
    const long long kvb   = (long long)b*262144 + h*64;

    // ---- stage Q (scaled by 0.125, split hi/lo) : [64][64]
    #pragma unroll
    for (int i = 0; i < 8; i++) {
        int f  = i * 128 + tid;
        int r  = f >> 4;
        int c4 = (f & 15) * 4;
        float4 v = *(const float4*)(g_qlin + qbase + (long long)r*512 + c4);
        v.x *= 0.125f; v.y *= 0.125f; v.z *= 0.125f; v.w *= 0.125f;
        float h0 = __bfloat162float(__float2bfloat16_rn(v.x));
        float h1 = __bfloat162float(__float2bfloat16_rn(v.y));
        float h2 = __bfloat162float(__float2bfloat16_rn(v.z));
        float h3 = __bfloat162float(__float2bfloat16_rn(v.w));
        uint2 ph = { pack_bf2(h0, h1), pack_bf2(h2, h3) };
        uint2 pl = { pack_bf2(v.x - h0, v.y - h1), pack_bf2(v.z - h2, v.w - h3) };
        *(uint2*)&sQh[r * PQ + c4] = ph;
        *(uint2*)&sQl[r * PQ + c4] = pl;
    }
    // ---- stage K (split hi/lo): [256 tokens][64 dims]
    #pragma unroll
    for (int i = 0; i < 32; i++) {
        int f  = i * 128 + tid;
        int r  = f >> 4;
        int c4 = (f & 15) * 4;
        float4 v = *(const float4*)(g_kvlin + kvb + (long long)r*1024 + c4);
        float h0 = __bfloat162float(__float2bfloat16_rn(v.x));
        float h1 = __bfloat162float(__float2bfloat16_rn(v.y));
        float h2 = __bfloat162float(__float2bfloat16_rn(v.z));
        float h3 = __bfloat162float(__float2bfloat16_rn(v.w));
        uint2 ph = { pack_bf2(h0, h1), pack_bf2(h2, h3) };
        uint2 pl = { pack_bf2(v.x - h0, v.y - h1), pack_bf2(v.z - h2, v.w - h3) };
        *(uint2*)&sKh[r * PK + c4] = ph;
        *(uint2*)&sKl[r * PK + c4] = pl;
    }
    __syncthreads();

    // ---- Phase 1: S = Q' K^T
    float acc[32][4];
    #pragma unroll
    for (int nf = 0; nf < 32; nf++)
        #pragma unroll
        for (int q = 0; q < 4; q++) acc[nf][q] = 0.0f;

    #pragma unroll
    for (int s = 0; s < 4; s++) {
        const int arow = wid*16 + (lane & 15);
        const int acol = s*16 + ((lane >> 4) << 3);
        uint32_t ah[4], al[4];
        ldm_x4(ah, smem_u32(&sQh[arow*PQ + acol]));
        ldm_x4(al, smem_u32(&sQl[arow*PQ + acol]));

        const int brow_base = (lane & 7) + ((lane >> 4) << 3);
        const int bcol      = s*16 + (((lane >> 3) & 1) << 3);
        #pragma unroll
        for (int np = 0; np < 16; np++) {
            uint32_t rh[4];
            ldm_x4(rh, smem_u32(&sKh[(np*16 + brow_base)*PK + bcol]));
            uint32_t b0[2] = { rh[0], rh[1] };
            uint32_t b1[2] = { rh[2], rh[3] };
            mma_bf16(acc[2*np],   ah, b0);
            mma_bf16(acc[2*np+1], ah, b1);
            mma_bf16(acc[2*np],   al, b0);
            mma_bf16(acc[2*np+1], al, b1);
            uint32_t rl[4];
            ldm_x4(rl, smem_u32(&sKl[(np*16 + brow_base)*PK + bcol]));
            uint32_t c0[2] = { rl[0], rl[1] };
            uint32_t c1[2] = { rl[2], rl[3] };
            mma_bf16(acc[2*np],   ah, c0);
            mma_bf16(acc[2*np+1], ah, c1);
        }
    }
    __syncthreads();   // all warps done reading K

    // ---- relative-position bias (gmem, L2-resident)
    {
        const int r0 = qt*64 + wid*16 + (lane >> 2);
        const float* br0 = g_bias + (long long)h*65536 + (long long)r0*256;
        const float* br8 = br0 + 8*256;
        const int cb = (lane & 3)*2;
        #pragma unroll
        for (int nf = 0; nf < 32; nf++) {
            float2 b0 = *(const float2*)&br0[nf*8 + cb];
            float2 b8 = *(const float2*)&br8[nf*8 + cb];
            acc[nf][0] += b0.x; acc[nf][1] += b0.y;
            acc[nf][2] += b8.x; acc[nf][3] += b8.y;
        }
    }

    // ---- softmax in registers (rows r0 = c0/c1, r0+8 = c2/c3)
    float mx0 = -1e30f, mx1 = -1e30f;
    #pragma unroll
    for (int nf = 0; nf < 32; nf++) {
        mx0 = fmaxf(mx0, fmaxf(acc[nf][0], acc[nf][1]));
        mx1 = fmaxf(mx1, fmaxf(acc[nf][2], acc[nf][3]));
    }
    mx0 = fmaxf(mx0, __shfl_xor_sync(0xffffffffu, mx0, 1));
    mx0 = fmaxf(mx0, __shfl_xor_sync(0xffffffffu, mx0, 2));
    mx1 = fmaxf(mx1, __shfl_xor_sync(0xffffffffu, mx1, 1));
    mx1 = fmaxf(mx1, __shfl_xor_sync(0xffffffffu, mx1, 2));

    float s0 = 0.0f, s1 = 0.0f;
    #pragma unroll
    for (int nf = 0; nf < 32; nf++) {
        acc[nf][0] = __expf(acc[nf][0] - mx0);
        acc[nf][1] = __expf(acc[nf][1] - mx0);
        acc[nf][2] = __expf(acc[nf][2] - mx1);
        acc[nf][3] = __expf(acc[nf][3] - mx1);
        s0 += acc[nf][0] + acc[nf][1];
        s1 += acc[nf][2] + acc[nf][3];
    }
    s0 += __shfl_xor_sync(0xffffffffu, s0, 1);
    s0 += __shfl_xor_sync(0xffffffffu, s0, 2);
    s1 += __shfl_xor_sync(0xffffffffu, s1, 1);
    s1 += __shfl_xor_sync(0xffffffffu, s1, 2);
    const float inv0 = 1.0f / s0;
    const float inv1 = 1.0f / s1;

    // convert P to hi/lo bf16 pairs (packed along k)
    uint32_t pH[32], pH8[32], pL[32], pL8[32];
    #pragma unroll
    for (int nf = 0; nf < 32; nf++) {
        float p0 = acc[nf][0]*inv0, p1 = acc[nf][1]*inv0;
        float p2 = acc[nf][2]*inv1, p3 = acc[nf][3]*inv1;
        float h0 = __bfloat162float(__float2bfloat16_rn(p0));
        float h1 = __bfloat162float(__float2bfloat16_rn(p1));
        float h2 = __bfloat162float(__float2bfloat16_rn(p2));
        float h3 = __bfloat162float(__float2bfloat16_rn(p3));
        pH [nf] = pack_bf2(h0, h1);
        pH8[nf] = pack_bf2(h2, h3);
        pL [nf] = pack_bf2(p0 - h0, p1 - h1);
        pL8[nf] = pack_bf2(p2 - h2, p3 - h3);
    }

    // ---- stage V (overwrites K region): [256 tokens][64 dims]
    #pragma unroll
    for (int i = 0; i < 32; i++) {
        int f  = i * 128 + tid;
        int r  = f >> 4;
        int c4 = (f & 15) * 4;
        float4 v = *(const float4*)(g_kvlin + kvb + 512 + (long long)r*1024 + c4);
        float h0 = __bfloat162float(__float2bfloat16_rn(v.x));
        float h1 = __bfloat162float(__float2bfloat16_rn(v.y));
        float h2 = __bfloat162float(__float2bfloat16_rn(v.z));
        float h3 = __bfloat162float(__float2bfloat16_rn(v.w));
        uint2 ph = { pack_bf2(h0, h1), pack_bf2(h2, h3) };
        uint2 pl = { pack_bf2(v.x - h0, v.y - h1), pack_bf2(v.z - h2, v.w - h3) };
        *(uint2*)&sKh[r * PK + c4] = ph;
        *(uint2*)&sKl[r * PK + c4] = pl;
    }
    __syncthreads();

    // ---- Phase 3: O = P V   (k = 256 tokens, n = 64 dims)
    float oacc[8][4];
    #pragma unroll
    for (int nf = 0; nf < 8; nf++)
        #pragma unroll
        for (int q = 0; q < 4; q++) oacc[nf][q] = 0.0f;

    #pragma unroll
    for (int s = 0; s < 16; s++) {
        uint32_t ah[4] = { pH[2*s], pH8[2*s], pH[2*s+1], pH8[2*s+1] };
        uint32_t al[4] = { pL[2*s], pL8[2*s], pL[2*s+1], pL8[2*s+1] };
        const int brow = s*16 + (lane & 15);
        #pragma unroll
        for (int np = 0; np < 4; np++) {
            int bcol = np*16 + ((lane >> 4) << 3);
            uint32_t rh[4];
            ldm_x4_t(rh, smem_u32(&sKh[brow*PK + bcol]));
            uint32_t b0[2] = { rh[0], rh[1] };
            uint32_t b1[2] = { rh[2], rh[3] };
            mma_bf16(oacc[2*np],   ah, b0);
            mma_bf16(oacc[2*np+1], ah, b1);
            mma_bf16(oacc[2*np],   al, b0);
            mma_bf16(oacc[2*np+1], al, b1);
            uint32_t rl[4];
            ldm_x4_t(rl, smem_u32(&sKl[brow*PK + bcol]));
            uint32_t c0[2] = { rl[0], rl[1] };
            uint32_t c1[2] = { rl[2], rl[3] };
            mma_bf16(oacc[2*np],   ah, c0);
            mma_bf16(oacc[2*np+1], ah, c1);
        }
    }

    // ---- epilogue: write O head-interleaved (fp32)
    const long long obase = (long long)b*131072 + (long long)(qt*64)*512 + h*64;
    {
        const int r0 = wid*16 + (lane >> 2);
        const int cb = (lane & 3)*2;
        #pragma unroll
        for (int nf = 0; nf < 8; nf++) {
            float2 v0 = { oacc[nf][0], oacc[nf][1] };
            float2 v1 = { oacc[nf][2], oacc[nf][3] };
            *(float2*)(g_o + obase + (long long)r0*512     + nf*8 + cb) = v0;
            *(float2*)(g_o + obase + (long long)(r0+8)*512 + nf*8 + cb) = v1;
        }
    }
}

// ---------------------------------------------------------------------------
// Relative-position bias matrix g_bias[h][i][j] from bias_table [961,8].
// ---------------------------------------------------------------------------
__global__ void __launch_bounds__(256)
k_build_bias(const float* __restrict__ table)
{
    int t = blockIdx.x * blockDim.x + threadIdx.x;
    int i = t >> 8, j = t & 255;
    int dh = (i >> 4) - (j >> 4) + 15;
    int dw = (i & 15) - (j & 15) + 15;
    int idx = dh * 31 + dw;
    #pragma unroll
    for (int h = 0; h < 8; h++)
        g_bias[(long long)h * 65536 + t] = table[idx * 8 + h];
}

// ---------------------------------------------------------------------------
extern "C" void kernel_launch(void* const* d_in, const int* in_sizes, int n_in,
                              void* d_out, int out_size)
{
    const float* x      = (const float*)d_in[0];
    const float* y      = (const float*)d_in[1];
    const float* q_w    = (const float*)d_in[2];
    const float* kv_w   = (const float*)d_in[3];
    const float* proj_w = (const float*)d_in[4];
    const float* proj_b = (const float*)d_in[5];
    const float* table  = (const float*)d_in[6];
    float* out = (float*)d_out;

    cudaFuncSetAttribute(k_attn_fused,
                         cudaFuncAttributeMaxDynamicSharedMemorySize, 92160);

    k_build_bias<<<256, 256>>>(table);

    // split weights once (harness pointers in, device globals bound in-kernel)
    k_split_wq <<<256, 256>>>((const float4*)q_w);
    k_split_wkv<<<512, 256>>>((const float4*)kv_w);
    k_split_wp <<<256, 256>>>((const float4*)proj_w);

    // split x -> q GEMM (fp32 q_lin out)
    k_split_in<<<16384, 256>>>((const float4*)x);
    k_gemm_q<<<dim3(4, 256, 1), 256>>>();

    // split y (reuse buffers) -> kv GEMM (fp32 kv_lin out)
    k_split_in<<<16384, 256>>>((const float4*)y);
    k_gemm_kv<<<dim3(8, 256, 1), 256>>>();

    // fused attention (fp32 O out)
    k_attn_fused<<<dim3(4, 8, 128), 128, 92160>>>();

    // split O -> proj GEMM (+bias, fp32 out)
    k_split_o<<<16384, 256>>>();
    k_gemm_proj<<<dim3(4, 256, 1), 256>>>(proj_b, out);
}

// round 16
// speedup vs baseline: 1.3329x; 1.3329x over previous
#include <cuda_runtime.h>
#include <cuda_bf16.h>
#include <math.h>
#include <stdint.h>

// Swin-style window cross-attention.
// B=128, N=256 (16x16 window), C=512, H=8, d=64.
// End-to-end split-bf16 dataflow; 3-term compensated bf16 MMA (drop lo*lo).
// RULE: device globals referenced ONLY inside device code.

// ---------------- scratch (device globals; no allocation) ------------------
__device__ __nv_bfloat16 g_inh[32768LL * 512];   // split x, then y
__device__ __nv_bfloat16 g_inl[32768LL * 512];
__device__ __nv_bfloat16 g_qh [32768LL * 512];   // 0.125-scaled q_lin (split)
__device__ __nv_bfloat16 g_ql [32768LL * 512];
__device__ __nv_bfloat16 g_kvh[32768LL * 1024];  // kv_lin (split)
__device__ __nv_bfloat16 g_kvl[32768LL * 1024];
__device__ __nv_bfloat16 g_oh [32768LL * 512];   // attention O (split)
__device__ __nv_bfloat16 g_ol [32768LL * 512];
__device__ __nv_bfloat16 g_wqh [512LL * 512],  g_wql [512LL * 512];
__device__ __nv_bfloat16 g_wkvh[512LL * 1024], g_wkvl[512LL * 1024];
__device__ __nv_bfloat16 g_wph [512LL * 512],  g_wpl [512LL * 512];
__device__ float g_bias[8LL * 256 * 256];        // [H,N,N]

// ---------------------------- helpers --------------------------------------
__device__ __forceinline__ uint32_t smem_u32(const void* p) {
    return (uint32_t)__cvta_generic_to_shared(p);
}
__device__ __forceinline__ uint32_t pack_bf2(float a, float b) {
    __nv_bfloat162 t = __floats2bfloat162_rn(a, b);
    return *reinterpret_cast<uint32_t*>(&t);
}
__device__ __forceinline__ void cp16(uint32_t dst, const void* src) {
    asm volatile("cp.async.cg.shared.global [%0], [%1], 16;" :: "r"(dst), "l"(src));
}
__device__ __forceinline__ void cp_commit() {
    asm volatile("cp.async.commit_group;");
}
template<int N_>
__device__ __forceinline__ void cp_wait() {
    asm volatile("cp.async.wait_group %0;" :: "n"(N_));
}
__device__ __forceinline__ void ldm_x4(uint32_t* r, uint32_t addr) {
    asm volatile("ldmatrix.sync.aligned.m8n8.x4.shared.b16 {%0,%1,%2,%3}, [%4];"
                 : "=r"(r[0]), "=r"(r[1]), "=r"(r[2]), "=r"(r[3]) : "r"(addr));
}
__device__ __forceinline__ void ldm_x4_t(uint32_t* r, uint32_t addr) {
    asm volatile("ldmatrix.sync.aligned.m8n8.x4.trans.shared.b16 {%0,%1,%2,%3}, [%4];"
                 : "=r"(r[0]), "=r"(r[1]), "=r"(r[2]), "=r"(r[3]) : "r"(addr));
}
__device__ __forceinline__ void mma_bf16(float* c, const uint32_t* a, const uint32_t* b) {
    asm volatile(
        "mma.sync.aligned.m16n8k16.row.col.f32.bf16.bf16.f32 "
        "{%0,%1,%2,%3}, {%4,%5,%6,%7}, {%8,%9}, {%0,%1,%2,%3};"
        : "+f"(c[0]), "+f"(c[1]), "+f"(c[2]), "+f"(c[3])
        : "r"(a[0]), "r"(a[1]), "r"(a[2]), "r"(a[3]), "r"(b[0]), "r"(b[1]));
}

// ---------------------------------------------------------------------------
// fp32 -> (hi, lo) bf16 split body + wrappers binding global destinations.
// ---------------------------------------------------------------------------
__device__ __forceinline__ void
split_body(const float4* __restrict__ src, uint2* __restrict__ hi,
           uint2* __restrict__ lo, int n4)
{
    int i = blockIdx.x * blockDim.x + threadIdx.x;
    if (i >= n4) return;
    float4 v = src[i];
    float h0 = __bfloat162float(__float2bfloat16_rn(v.x));
    float h1 = __bfloat162float(__float2bfloat16_rn(v.y));
    float h2 = __bfloat162float(__float2bfloat16_rn(v.z));
    float h3 = __bfloat162float(__float2bfloat16_rn(v.w));
    hi[i] = make_uint2(pack_bf2(h0, h1), pack_bf2(h2, h3));
    lo[i] = make_uint2(pack_bf2(v.x - h0, v.y - h1), pack_bf2(v.z - h2, v.w - h3));
}

__global__ void __launch_bounds__(256)
k_split_in(const float4* __restrict__ src)
{
    split_body(src, (uint2*)g_inh, (uint2*)g_inl, 4194304);
}
__global__ void __launch_bounds__(256)
k_split_wq(const float4* __restrict__ w)
{
    split_body(w, (uint2*)g_wqh, (uint2*)g_wql, 65536);
}
__global__ void __launch_bounds__(256)
k_split_wkv(const float4* __restrict__ w)
{
    split_body(w, (uint2*)g_wkvh, (uint2*)g_wkvl, 131072);
}
__global__ void __launch_bounds__(256)
k_split_wp(const float4* __restrict__ w)
{
    split_body(w, (uint2*)g_wph, (uint2*)g_wpl, 65536);
}

// ---------------------------------------------------------------------------
// Split-bf16 tensor-core GEMM, cp.async double-buffered.
// CTA tile 128x128, BK=32, 256 threads, 8 warps (4m x 2n), warp 32x64.
//   EPI=1: fp32 out + column bias
//   EPI=2: split bf16 out
//   EPI=3: split bf16 out, scaled by 0.125
// ---------------------------------------------------------------------------
template<int EPI, int M, int N, int K, int LDA, int LDB, int LDC>
__device__ __forceinline__ void
gemm2_body(const __nv_bfloat16* __restrict__ Ah, const __nv_bfloat16* __restrict__ Al,
           const __nv_bfloat16* __restrict__ Bh, const __nv_bfloat16* __restrict__ Bl,
           float* __restrict__ Cf,
           __nv_bfloat16* __restrict__ Ch, __nv_bfloat16* __restrict__ Cl,
           const float* __restrict__ bias)
{
    constexpr int PA = 40, PB = 136;
    constexpr int STG = 128*PA*2 + 32*PB*2;   // 18944 elems per stage
    extern __shared__ __nv_bfloat16 smb[];

    const int tid  = threadIdx.x;
    const int wid  = tid >> 5;
    const int lane = tid & 31;
    const int wm   = wid >> 1;
    const int wn   = wid & 1;
    const int row0 = blockIdx.y * 128;
    const int col0 = blockIdx.x * 128;

    float acc[2][8][4];
    #pragma unroll
    for (int i = 0; i < 2; i++)
        #pragma unroll
        for (int j = 0; j < 8; j++)
            #pragma unroll
            for (int q = 0; q < 4; q++) acc[i][j][q] = 0.0f;

    auto load_stage = [&](int k0, int s) {
        __nv_bfloat16* dAh = smb + s * STG;
        __nv_bfloat16* dAl = dAh + 128*PA;
        __nv_bfloat16* dBh = dAh + 256*PA;
        __nv_bfloat16* dBl = dBh + 32*PB;
        #pragma unroll
        for (int i = 0; i < 2; i++) {
            int idx = i * 256 + tid;
            int r   = idx >> 2;
            int c8  = (idx & 3) * 8;
            long long ga = (long long)(row0 + r) * LDA + k0 + c8;
            cp16(smem_u32(dAh + r*PA + c8), Ah + ga);
            cp16(smem_u32(dAl + r*PA + c8), Al + ga);
            int rb  = idx >> 4;
            int cb8 = (idx & 15) * 8;
            long long gb = (long long)(k0 + rb) * LDB + col0 + cb8;
            cp16(smem_u32(dBh + rb*PB + cb8), Bh + gb);
            cp16(smem_u32(dBl + rb*PB + cb8), Bl + gb);
        }
    };

    constexpr int NC = K / 32;
    load_stage(0, 0);
    cp_commit();

    for (int c = 0; c < NC; c++) {
        if (c + 1 < NC) load_stage((c + 1) * 32, (c + 1) & 1);
        cp_commit();
        if (c + 1 < NC) cp_wait<1>(); else cp_wait<0>();
        __syncthreads();

        const __nv_bfloat16* sAh = smb + (c & 1) * STG;
        const __nv_bfloat16* sAl = sAh + 128*PA;
        const __nv_bfloat16* sBh = sAh + 256*PA;
        const __nv_bfloat16* sBl = sBh + 32*PB;

        #pragma unroll
        for (int ks = 0; ks < 2; ks++) {
            const int arow = wm * 32 + (lane & 15);
            const int acol = ks * 16 + ((lane >> 4) << 3);
            const int brow = ks * 16 + (lane & 15);

            uint32_t ah[2][4], al[2][4], bb[8][2];

            #pragma unroll
            for (int mf = 0; mf < 2; mf++)
                ldm_x4(ah[mf], smem_u32(&sAh[(arow + mf*16)*PA + acol]));
            #pragma unroll
            for (int np = 0; np < 4; np++) {
                uint32_t r[4];
                int bcol = wn * 64 + np * 16 + ((lane >> 4) << 3);
                ldm_x4_t(r, smem_u32(&sBh[brow*PB + bcol]));
                bb[2*np][0] = r[0]; bb[2*np][1] = r[1];
                bb[2*np+1][0] = r[2]; bb[2*np+1][1] = r[3];
            }
            #pragma unroll
            for (int mf = 0; mf < 2; mf++)
                #pragma unroll
                for (int nf = 0; nf < 8; nf++)
                    mma_bf16(acc[mf][nf], ah[mf], bb[nf]);

            #pragma unroll
            for (int mf = 0; mf < 2; mf++)
                ldm_x4(al[mf], smem_u32(&sAl[(arow + mf*16)*PA + acol]));
            #pragma unroll
            for (int mf = 0; mf < 2; mf++)
                #pragma unroll
                for (int nf = 0; nf < 8; nf++)
                    mma_bf16(acc[mf][nf], al[mf], bb[nf]);

            #pragma unroll
            for (int np = 0; np < 4; np++) {
                uint32_t r[4];
                int bcol = wn * 64 + np * 16 + ((lane >> 4) << 3);
                ldm_x4_t(r, smem_u32(&sBl[brow*PB + bcol]));
                bb[2*np][0] = r[0]; bb[2*np][1] = r[1];
                bb[2*np+1][0] = r[2]; bb[2*np+1][1] = r[3];
            }
            #pragma unroll
            for (int mf = 0; mf < 2; mf++)
                #pragma unroll
                for (int nf = 0; nf < 8; nf++)
                    mma_bf16(acc[mf][nf], ah[mf], bb[nf]);
        }
        __syncthreads();
    }

    // ---- epilogue
    const float sc = (EPI == 3) ? 0.125f : 1.0f;
    #pragma unroll
    for (int mf = 0; mf < 2; mf++) {
        #pragma unroll
        for (int nf = 0; nf < 8; nf++) {
            int r = row0 + wm*32 + mf*16 + (lane >> 2);
            int c = col0 + wn*64 + nf*8 + (lane & 3)*2;
            if (EPI == 1) {
                float2 v0 = { acc[mf][nf][0] + bias[c], acc[mf][nf][1] + bias[c+1] };
                float2 v1 = { acc[mf][nf][2] + bias[c], acc[mf][nf][3] + bias[c+1] };
                *(float2*)(Cf + (long long)r*LDC + c)     = v0;
                *(float2*)(Cf + (long long)(r+8)*LDC + c) = v1;
            } else {
                float a0 = acc[mf][nf][0]*sc, a1 = acc[mf][nf][1]*sc;
                float a2 = acc[mf][nf][2]*sc, a3 = acc[mf][nf][3]*sc;
                float h0 = __bfloat162float(__float2bfloat16_rn(a0));
                float h1 = __bfloat162float(__float2bfloat16_rn(a1));
                float h2 = __bfloat162float(__float2bfloat16_rn(a2));
                float h3 = __bfloat162float(__float2bfloat16_rn(a3));
                *(uint32_t*)(Ch + (long long)r*LDC + c)     = pack_bf2(h0, h1);
                *(uint32_t*)(Cl + (long long)r*LDC + c)     = pack_bf2(a0-h0, a1-h1);
                *(uint32_t*)(Ch + (long long)(r+8)*LDC + c) = pack_bf2(h2, h3);
                *(uint32_t*)(Cl + (long long)(r+8)*LDC + c) = pack_bf2(a2-h2, a3-h3);
            }
        }
    }
}

// GEMM wrappers: bind device globals INSIDE device code.
__global__ void __launch_bounds__(256, 2)
k_gemm_q()
{
    gemm2_body<3, 32768,512,512, 512,512,512>(
        g_inh, g_inl, g_wqh, g_wql, nullptr, g_qh, g_ql, nullptr);
}
__global__ void __launch_bounds__(256, 2)
k_gemm_kv()
{
    gemm2_body<2, 32768,1024,512, 512,1024,1024>(
        g_inh, g_inl, g_wkvh, g_wkvl, nullptr, g_kvh, g_kvl, nullptr);
}
__global__ void __launch_bounds__(256, 2)
k_gemm_proj(const float* __restrict__ proj_b, float* __restrict__ out)
{
    gemm2_body<1, 32768,512,512, 512,512,512>(
        g_oh, g_ol, g_wph, g_wpl, out, nullptr, nullptr, proj_b);
}

// ---------------------------------------------------------------------------
// Fused attention, tensor-core, pre-split I/O (raw cp.async staging).
// CTA = (q-tile 64, head, batch); 128 threads = 4 warps; warp owns 16 q-rows
// and the full 256-wide score stripe (softmax in registers).
// smem 90KB: Qh/Ql [64][72], Kh/Kl [256][72] (reused for V).
// ---------------------------------------------------------------------------
__global__ void __launch_bounds__(128)
k_attn_fused()
{
    constexpr int PQ = 72, PK = 72;
    extern __shared__ __nv_bfloat16 smb[];
    __nv_bfloat16* sQh = smb;
    __nv_bfloat16* sQl = smb + 4608;
    __nv_bfloat16* sKh = smb + 9216;
    __nv_bfloat16* sKl = smb + 27648;

    const int tid  = threadIdx.x;
    const int wid  = tid >> 5;
    const int lane = tid & 31;
    const int qt   = blockIdx.x;
    const int h    = blockIdx.y;
    const int b    = blockIdx.z;

    const long long qbase = (long long)b*131072 + (long long)(qt*64)*512 + h*64;
    const long long kvb   = (long long)b*262144 + h*64;

    // stage Q + K via cp.async (raw bf16 copies)
    #pragma unroll
    for (int i = 0; i < 4; i++) {
        int idx = i*128 + tid;
        int r = idx >> 3, c8 = (idx & 7)*8;
        long long g = qbase + (long long)r*512 + c8;
        cp16(smem_u32(sQh + r*PQ + c8), g_qh + g);
        cp16(smem_u32(sQl + r*PQ + c8), g_ql + g);
    }
    #pragma unroll
    for (int i = 0; i < 16; i++) {
        int idx = i*128 + tid;
        int r = idx >> 3, c8 = (idx & 7)*8;
        long long g = kvb + (long long)r*1024 + c8;
        cp16(smem_u32(sKh + r*PK + c8), g_kvh + g);
        cp16(smem_u32(sKl + r*PK + c8), g_kvl + g);
    }
    cp_commit();
    cp_wait<0>();
    __syncthreads();

    // ---- Phase 1: S = Q' K^T
    float acc[32][4];
    #pragma unroll
    for (int nf = 0; nf < 32; nf++)
        #pragma unroll
        for (int q = 0; q < 4; q++) acc[nf][q] = 0.0f;

    #pragma unroll
    for (int s = 0; s < 4; s++) {
        const int arow = wid*16 + (lane & 15);
        const int acol = s*16 + ((lane >> 4) << 3);
        uint32_t ah[4], al[4];
        ldm_x4(ah, smem_u32(&sQh[arow*PQ + acol]));
        ldm_x4(al, smem_u32(&sQl[arow*PQ + acol]));

        const int brow_base = (lane & 7) + ((lane >> 4) << 3);
        const int bcol      = s*16 + (((lane >> 3) & 1) << 3);
        #pragma unroll
        for (int np = 0; np < 16; np++) {
            uint32_t rh[4];
            ldm_x4(rh, smem_u32(&sKh[(np*16 + brow_base)*PK + bcol]));
            uint32_t b0[2] = { rh[0], rh[1] };
            uint32_t b1[2] = { rh[2], rh[3] };
            mma_bf16(acc[2*np],   ah, b0);
            mma_bf16(acc[2*np+1], ah, b1);
            mma_bf16(acc[2*np],   al, b0);
            mma_bf16(acc[2*np+1], al, b1);
            uint32_t rl[4];
            ldm_x4(rl, smem_u32(&sKl[(np*16 + brow_base)*PK + bcol]));
            uint32_t c0[2] = { rl[0], rl[1] };
            uint32_t c1[2] = { rl[2], rl[3] };
            mma_bf16(acc[2*np],   ah, c0);
            mma_bf16(acc[2*np+1], ah, c1);
        }
    }
    __syncthreads();   // all warps done reading K

    // ---- issue V loads now (overlap with bias + softmax + P conversion)
    #pragma unroll
    for (int i = 0; i < 16; i++) {
        int idx = i*128 + tid;
        int r = idx >> 3, c8 = (idx & 7)*8;
        long long g = kvb + 512 + (long long)r*1024 + c8;
        cp16(smem_u32(sKh + r*PK + c8), g_kvh + g);
        cp16(smem_u32(sKl + r*PK + c8), g_kvl + g);
    }
    cp_commit();

    // ---- relative-position bias
    {
        const int r0 = qt*64 + wid*16 + (lane >> 2);
        const float* br0 = g_bias + (long long)h*65536 + (long long)r0*256;
        const float* br8 = br0 + 8*256;
        const int cb = (lane & 3)*2;
        #pragma unroll
        for (int nf = 0; nf < 32; nf++) {
            float2 b0 = *(const float2*)&br0[nf*8 + cb];
            float2 b8 = *(const float2*)&br8[nf*8 + cb];
            acc[nf][0] += b0.x; acc[nf][1] += b0.y;
            acc[nf][2] += b8.x; acc[nf][3] += b8.y;
        }
    }

    // ---- softmax in registers
    float mx0 = -1e30f, mx1 = -1e30f;
    #pragma unroll
    for (int nf = 0; nf < 32; nf++) {
        mx0 = fmaxf(mx0, fmaxf(acc[nf][0], acc[nf][1]));
        mx1 = fmaxf(mx1, fmaxf(acc[nf][2], acc[nf][3]));
    }
    mx0 = fmaxf(mx0, __shfl_xor_sync(0xffffffffu, mx0, 1));
    mx0 = fmaxf(mx0, __shfl_xor_sync(0xffffffffu, mx0, 2));
    mx1 = fmaxf(mx1, __shfl_xor_sync(0xffffffffu, mx1, 1));
    mx1 = fmaxf(mx1, __shfl_xor_sync(0xffffffffu, mx1, 2));

    float s0 = 0.0f, s1 = 0.0f;
    #pragma unroll
    for (int nf = 0; nf < 32; nf++) {
        acc[nf][0] = __expf(acc[nf][0] - mx0);
        acc[nf][1] = __expf(acc[nf][1] - mx0);
        acc[nf][2] = __expf(acc[nf][2] - mx1);
        acc[nf][3] = __expf(acc[nf][3] - mx1);
        s0 += acc[nf][0] + acc[nf][1];
        s1 += acc[nf][2] + acc[nf][3];
    }
    s0 += __shfl_xor_sync(0xffffffffu, s0, 1);
    s0 += __shfl_xor_sync(0xffffffffu, s0, 2);
    s1 += __shfl_xor_sync(0xffffffffu, s1, 1);
    s1 += __shfl_xor_sync(0xffffffffu, s1, 2);
    const float inv0 = 1.0f / s0;
    const float inv1 = 1.0f / s1;

    uint32_t pH[32], pH8[32], pL[32], pL8[32];
    #pragma unroll
    for (int nf = 0; nf < 32; nf++) {
        float p0 = acc[nf][0]*inv0, p1 = acc[nf][1]*inv0;
        float p2 = acc[nf][2]*inv1, p3 = acc[nf][3]*inv1;
        float h0 = __bfloat162float(__float2bfloat16_rn(p0));
        float h1 = __bfloat162float(__float2bfloat16_rn(p1));
        float h2 = __bfloat162float(__float2bfloat16_rn(p2));
        float h3 = __bfloat162float(__float2bfloat16_rn(p3));
        pH [nf] = pack_bf2(h0, h1);
        pH8[nf] = pack_bf2(h2, h3);
        pL [nf] = pack_bf2(p0 - h0, p1 - h1);
        pL8[nf] = pack_bf2(p2 - h2, p3 - h3);
    }

    cp_wait<0>();
    __syncthreads();   // V ready

    // ---- Phase 3: O = P V
    float oacc[8][4];
    #pragma unroll
    for (int nf = 0; nf < 8; nf++)
        #pragma unroll
        for (int q = 0; q < 4; q++) oacc[nf][q] = 0.0f;

    #pragma unroll
    for (int s = 0; s < 16; s++) {
        uint32_t ah[4] = { pH[2*s], pH8[2*s], pH[2*s+1], pH8[2*s+1] };
        uint32_t al[4] = { pL[2*s], pL8[2*s], pL[2*s+1], pL8[2*s+1] };
        const int brow = s*16 + (lane & 15);
        #pragma unroll
        for (int np = 0; np < 4; np++) {
            int bcol = np*16 + ((lane >> 4) << 3);
            uint32_t rh[4];
            ldm_x4_t(rh, smem_u32(&sKh[brow*PK + bcol]));
            uint32_t b0[2] = { rh[0], rh[1] };
            uint32_t b1[2] = { rh[2], rh[3] };
            mma_bf16(oacc[2*np],   ah, b0);
            mma_bf16(oacc[2*np+1], ah, b1);
            mma_bf16(oacc[2*np],   al, b0);
            mma_bf16(oacc[2*np+1], al, b1);
            uint32_t rl[4];
            ldm_x4_t(rl, smem_u32(&sKl[brow*PK + bcol]));
            uint32_t c0[2] = { rl[0], rl[1] };
            uint32_t c1[2] = { rl[2], rl[3] };
            mma_bf16(oacc[2*np],   ah, c0);
            mma_bf16(oacc[2*np+1], ah, c1);
        }
    }

    // ---- epilogue: split O, head-interleaved, into g_oh/g_ol
    const long long obase = (long long)b*131072 + (long long)(qt*64)*512 + h*64;
    {
        const int r0 = wid*16 + (lane >> 2);
        const int cb = (lane & 3)*2;
        #pragma unroll
        for (int nf = 0; nf < 8; nf++) {
            float a0 = oacc[nf][0], a1 = oacc[nf][1];
            float a2 = oacc[nf][2], a3 = oacc[nf][3];
            float h0 = __bfloat162float(__float2bfloat16_rn(a0));
            float h1 = __bfloat162float(__float2bfloat16_rn(a1));
            float h2 = __bfloat162float(__float2bfloat16_rn(a2));
            float h3 = __bfloat162float(__float2bfloat16_rn(a3));
            *(uint32_t*)(g_oh + obase + (long long)r0*512     + nf*8 + cb) = pack_bf2(h0, h1);
            *(uint32_t*)(g_ol + obase + (long long)r0*512     + nf*8 + cb) = pack_bf2(a0-h0, a1-h1);
            *(uint32_t*)(g_oh + obase + (long long)(r0+8)*512 + nf*8 + cb) = pack_bf2(h2, h3);
            *(uint32_t*)(g_ol + obase + (long long)(r0+8)*512 + nf*8 + cb) = pack_bf2(a2-h2, a3-h3);
        }
    }
}

// ---------------------------------------------------------------------------
// Relative-position bias matrix g_bias[h][i][j] from bias_table [961,8].
// ---------------------------------------------------------------------------
__global__ void __launch_bounds__(256)
k_build_bias(const float* __restrict__ table)
{
    int t = blockIdx.x * blockDim.x + threadIdx.x;
    int i = t >> 8, j = t & 255;
    int dh = (i >> 4) - (j >> 4) + 15;
    int dw = (i & 15) - (j & 15) + 15;
    int idx = dh * 31 + dw;
    #pragma unroll
    for (int h = 0; h < 8; h++)
        g_bias[(long long)h * 65536 + t] = table[idx * 8 + h];
}

// ---------------------------------------------------------------------------
extern "C" void kernel_launch(void* const* d_in, const int* in_sizes, int n_in,
                              void* d_out, int out_size)
{
    const float* x      = (const float*)d_in[0];
    const float* y      = (const float*)d_in[1];
    const float* q_w    = (const float*)d_in[2];
    const float* kv_w   = (const float*)d_in[3];
    const float* proj_w = (const float*)d_in[4];
    const float* proj_b = (const float*)d_in[5];
    const float* table  = (const float*)d_in[6];
    float* out = (float*)d_out;

    constexpr int GSMEM = (128*40*2 + 32*136*2) * 2 * 2;  // 75776 B
    cudaFuncSetAttribute(k_gemm_q,
                         cudaFuncAttributeMaxDynamicSharedMemorySize, GSMEM);
    cudaFuncSetAttribute(k_gemm_kv,
                         cudaFuncAttributeMaxDynamicSharedMemorySize, GSMEM);
    cudaFuncSetAttribute(k_gemm_proj,
                         cudaFuncAttributeMaxDynamicSharedMemorySize, GSMEM);
    cudaFuncSetAttribute(k_attn_fused,
                         cudaFuncAttributeMaxDynamicSharedMemorySize, 92160);

    k_build_bias<<<256, 256>>>(table);

    // split weights once
    k_split_wq <<<256, 256>>>((const float4*)q_w);
    k_split_wkv<<<512, 256>>>((const float4*)kv_w);
    k_split_wp <<<256, 256>>>((const float4*)proj_w);

    // split x -> q GEMM (0.125-prescaled, split out)
    k_split_in<<<16384, 256>>>((const float4*)x);
    k_gemm_q<<<dim3(4, 256, 1), 256, GSMEM>>>();

    // split y (reuse buffers) -> kv GEMM (split out)
    k_split_in<<<16384, 256>>>((const float4*)y);
    k_gemm_kv<<<dim3(8, 256, 1), 256, GSMEM>>>();

    // fused attention (split O out)
    k_attn_fused<<<dim3(4, 8, 128), 128, 92160>>>();

    // out = o @ proj_w + proj_b (fp32 out)
    k_gemm_proj<<<dim3(4, 256, 1), 256, GSMEM>>>(proj_b, out);
}